// round 12
// baseline (speedup 1.0000x reference)
#include <cuda_runtime.h>
#include <cuda_fp16.h>
#include <cstdint>

#define B_ 8192
#define I_ 1024
#define H_ 2048
#define BETA32 ((float)0.9512294245007140)
#define MARGIN 2e-3f
#define FLAG_CAP (4 * 1024 * 1024)

typedef unsigned int uint;

// ---------------- device-global scratch (no mallocs allowed) ----------------
__device__ float  g_gen_mem[(size_t)B_ * I_];
__device__ float  g_inf_mem[(size_t)B_ * H_];
__device__ unsigned char g_lr1[(size_t)B_ * I_];    // last-reset step, gen layer
__device__ unsigned char g_lr2[(size_t)B_ * H_];    // last-reset step, inf layer
__device__ float  g_X1hist[(size_t)5 * B_ * H_];    // exact LN(current) per step
__device__ float  g_X2hist[(size_t)5 * B_ * I_];    // exact LN(error) per step
__device__ __half g_X1h[(size_t)B_ * H_];           // fp16(hi) of LN(current)
__device__ __half g_X2h[(size_t)B_ * I_];
__device__ __half g_W1h[(size_t)I_ * H_];           // ternary fp16: rows n=i, cols k=h
__device__ __half g_W2h[(size_t)H_ * I_];           // ternary fp16: rows n=h, cols k=i
__device__ float  g_WQ[(size_t)I_ * H_];            // exact wq [i][h]
__device__ float  g_W1T[(size_t)H_ * I_];           // exact wq^T [h][i]
__device__ double g_partials[512];
__device__ int    g_qcnt;
__device__ int    g_qcnt2;
__device__ volatile int g_ready;
__device__ float  g_sc[2];                          // [0]=scale, [1]=scale+eps
__device__ int    g_flag_cnt[12];
__device__ uint   g_flags[2][FLAG_CAP];

// ---------------- helpers ----------------
__device__ __forceinline__ double warp_sumd(double v) {
#pragma unroll
    for (int o = 16; o; o >>= 1) v += __shfl_xor_sync(0xffffffffu, v, o);
    return v;
}
__device__ __forceinline__ void two_sum(float a, float b, float& s, float& e) {
    s = __fadd_rn(a, b);
    float bp = __fsub_rn(s, a);
    e = __fadd_rn(__fsub_rn(a, __fsub_rn(s, bp)), __fsub_rn(b, bp));
}
__device__ __forceinline__ void kahan_add(float v, float& s, float& c) {
    float t, e;
    two_sum(s, v, t, e);
    s = t;
    c = __fadd_rn(c, e);
}
__device__ __forceinline__ void cp16(void* sm, const void* gm) {
    uint32_t s = (uint32_t)__cvta_generic_to_shared(sm);
    asm volatile("cp.async.cg.shared.global [%0], [%1], 16;\n" ::"r"(s), "l"(gm));
}
__device__ __forceinline__ void ldm4(uint32_t r[4], const __half* p) {
    uint32_t a = (uint32_t)__cvta_generic_to_shared(p);
    asm volatile("ldmatrix.sync.aligned.m8n8.x4.shared.b16 {%0,%1,%2,%3},[%4];\n"
                 : "=r"(r[0]), "=r"(r[1]), "=r"(r[2]), "=r"(r[3]) : "r"(a));
}
__device__ __forceinline__ void mma16816(float c[4], const uint32_t a[4], uint32_t b0, uint32_t b1) {
    asm volatile(
        "mma.sync.aligned.m16n8k16.row.col.f32.f16.f16.f32 "
        "{%0,%1,%2,%3},{%4,%5,%6,%7},{%8,%9},{%0,%1,%2,%3};\n"
        : "+f"(c[0]), "+f"(c[1]), "+f"(c[2]), "+f"(c[3])
        : "r"(a[0]), "r"(a[1]), "r"(a[2]), "r"(a[3]), "r"(b0), "r"(b1));
}

// ---------------- fused |W| reduce + scale + quantize (persistent, self-resetting) ----------------
// 512 blocks x 256 thr: all co-resident (<= 8 blocks/SM) so the spin-release is deadlock-free.
__global__ __launch_bounds__(256) void reduce_quant_kernel(const float* __restrict__ W) {
    // ---- phase 1: |W| sum (deterministic fixed-order combine) ----
    double s = 0.0;
    for (int i = blockIdx.x * blockDim.x + threadIdx.x; i < I_ * H_; i += gridDim.x * blockDim.x)
        s += (double)fabsf(W[i]);
    s = warp_sumd(s);
    __shared__ double sh[8];
    __shared__ bool amLast;
    int lane = threadIdx.x & 31, wid = threadIdx.x >> 5;
    if (lane == 0) sh[wid] = s;
    __syncthreads();
    if (threadIdx.x == 0) {
        double t = 0.0;
        for (int i = 0; i < 8; i++) t += sh[i];
        g_partials[blockIdx.x] = t;
        __threadfence();
        int prev = atomicAdd(&g_qcnt, 1);
        amLast = (prev == (int)gridDim.x - 1);
    }
    __syncthreads();
    if (amLast && threadIdx.x == 0) {
        double t = 0.0;
        for (int i = 0; i < 512; i++) t += g_partials[i];   // fixed order -> deterministic
        float Sf = (float)t;
        float scale = Sf / 2097152.0f;                      // exact (2^21)
        g_sc[0] = scale;
        g_sc[1] = __fadd_rn(scale, 1e-5f);
        g_qcnt = 0;                                         // reset for next replay
        __threadfence();
        g_ready = 1;                                        // release all blocks
    }
    // ---- spin until scale is published ----
    if (threadIdx.x == 0) {
        while (g_ready == 0) {}
    }
    __syncthreads();
    float d = ((volatile float*)g_sc)[1];
    float sc = ((volatile float*)g_sc)[0];
    // ---- phase 2: quantize (grid-stride over I_*H_) ----
    for (int idx = blockIdx.x * 256 + threadIdx.x; idx < I_ * H_; idx += 512 * 256) {
        float t = rintf(W[idx] / d);                        // CR div + round-half-even
        t = fminf(1.f, fmaxf(-1.f, t));
        float wq = __fmul_rn(t, sc);                        // exact (t in {-1,0,1})
        int i = idx >> 11;
        int h = idx & (H_ - 1);
        g_WQ[(size_t)i * H_ + h] = wq;
        g_W1T[(size_t)h * I_ + i] = wq;
        __half th = __float2half_rn(t);
        g_W1h[(size_t)i * H_ + h] = th;
        g_W2h[(size_t)h * I_ + i] = th;
    }
    // ---- reset release flag for the next graph replay ----
    __threadfence();
    if (threadIdx.x == 0) {
        int prev2 = atomicAdd(&g_qcnt2, 1);
        if (prev2 == (int)gridDim.x - 1) {
            g_ready = 0;
            g_qcnt2 = 0;
        }
    }
}

// ---------------- layer norm (Kahan fp32 stats; eager-XLA-exact elementwise) ----------------
template <int N, int WHICH>
__global__ __launch_bounds__(256) void ln_kernel(const float* __restrict__ x,
                                                 const float* __restrict__ g,
                                                 const float* __restrict__ bb,
                                                 int step, float* __restrict__ cur, int first) {
    constexpr int PER = N / 256;
    const int b = blockIdx.x;
    const float* xr = x + (size_t)b * N;
    float* hist = ((WHICH == 1) ? g_X1hist : g_X2hist) + ((size_t)step * B_ + b) * N;
    __half* yh = ((WHICH == 1) ? g_X1h : g_X2h) + (size_t)b * N;
    float v[PER];
    float s = 0.f, sc = 0.f;
#pragma unroll
    for (int j = 0; j < PER; j++) {
        float t = xr[threadIdx.x + j * 256];
        v[j] = t;
        kahan_add(t, s, sc);
    }
#pragma unroll
    for (int o = 16; o; o >>= 1) {
        float so = __shfl_xor_sync(0xffffffffu, s, o);
        float co = __shfl_xor_sync(0xffffffffu, sc, o);
        float t, e;
        two_sum(s, so, t, e);
        s = t;
        sc = __fadd_rn(sc, __fadd_rn(co, e));
    }
    __shared__ float shs[8], shc[8];
    __shared__ float fmu, frstd;
    int lane = threadIdx.x & 31, wid = threadIdx.x >> 5;
    if (lane == 0) { shs[wid] = s; shc[wid] = sc; }
    __syncthreads();
    if (threadIdx.x == 0) {
        double a = 0.0;
        for (int i = 0; i < 8; i++) a += (double)shs[i] + (double)shc[i];
        float Sf = (float)a;                     // ~CR f32 sum
        fmu = Sf / (float)N;                     // exact (N power of 2)
    }
    __syncthreads();
    float mu = fmu;
    float s2 = 0.f, s2c = 0.f;
#pragma unroll
    for (int j = 0; j < PER; j++) {
        float d = __fsub_rn(v[j], mu);
        float dd = __fmul_rn(d, d);
        kahan_add(dd, s2, s2c);
    }
#pragma unroll
    for (int o = 16; o; o >>= 1) {
        float so = __shfl_xor_sync(0xffffffffu, s2, o);
        float co = __shfl_xor_sync(0xffffffffu, s2c, o);
        float t, e;
        two_sum(s2, so, t, e);
        s2 = t;
        s2c = __fadd_rn(s2c, __fadd_rn(co, e));
    }
    if (lane == 0) { shs[wid] = s2; shc[wid] = s2c; }
    __syncthreads();
    if (threadIdx.x == 0) {
        double b2 = 0.0;
        for (int i = 0; i < 8; i++) b2 += (double)shs[i] + (double)shc[i];
        float S2f = (float)b2;
        float var = S2f / (float)N;              // exact
        float vp = __fadd_rn(var, 1e-5f);
        frstd = __fdiv_rn(1.0f, __fsqrt_rn(vp));
    }
    __syncthreads();
    float mu2 = fmu;
    float rstd = frstd;
#pragma unroll
    for (int j = 0; j < PER; j++) {
        int c = threadIdx.x + j * 256;
        float t1 = __fsub_rn(v[j], mu2);
        float t2 = __fmul_rn(t1, rstd);
        float t3 = __fmul_rn(t2, g[c]);          // separate mul (no fma)
        float yv = __fadd_rn(t3, bb[c]);         // separate add
        hist[c] = yv;                            // exact fp32 for fix kernel
        yh[c] = __float2half_rn(yv);             // hi only (fix covers the tail)
    }
    if (WHICH == 1 && first) {                   // step-0: fold in init
        for (int c = threadIdx.x; c < H_; c += 256) {
            size_t ii = (size_t)b * H_ + c;
            cur[ii] = xr[c];
            g_inf_mem[ii] = 0.f;
            g_lr2[ii] = 0;
        }
        for (int c = threadIdx.x; c < I_; c += 256) {
            size_t ii = (size_t)b * I_ + c;
            g_gen_mem[ii] = 0.f;
            g_lr1[ii] = 0;
        }
        if (b == 0 && threadIdx.x < 12) g_flag_cnt[threadIdx.x] = 0;
    }
}

// ---------------- fast tensor GEMM (fp16 hi-only, fp32 acc), persistent CTAs, BK=64 ----------------
template <int EPI, int KT, int NT>
__global__ __launch_bounds__(256, 2) void gemm_fast(
    const float* __restrict__ bgen, const float* __restrict__ bu,
    const float* __restrict__ errscale, float* __restrict__ cur,
    float* __restrict__ err, float* __restrict__ comb, float* __restrict__ pred,
    int step, int last) {
    const __half* Ag = (EPI == 1) ? g_X1h : g_X2h;
    const __half* Bg = (EPI == 1) ? g_W1h : g_W2h;
    constexpr int BK = 64;
    constexpr int LDS = 72;
    constexpr int TILES = KT / BK;
    constexpr int TN = NT / 128;
    constexpr int NTILES = (B_ / 128) * TN;

    extern __shared__ __align__(16) __half smem_h[];
    __half* sAp = smem_h;                        // [2][128][LDS]
    __half* sBp = smem_h + 2 * 128 * LDS;        // [2][128][LDS]
#define SA(st, r, c) sAp[((st) * 128 + (r)) * LDS + (c)]
#define SB(st, r, c) sBp[((st) * 128 + (r)) * LDS + (c)]

    const int tid = threadIdx.x;
    const int lane = tid & 31, wid = tid >> 5;
    const int wm = (wid & 3) * 32, wn = (wid >> 2) * 64;
    const float scale = g_sc[0];
    const float es = (EPI == 1) ? *errscale : 0.f;
    int* cnt = &g_flag_cnt[step * 2 + (EPI - 1)];

    for (int tile = blockIdx.x; tile < NTILES; tile += gridDim.x) {
        const int mb = tile / TN, nb = tile % TN;
        const int bm0 = mb * 128, bn0 = nb * 128;

        float acc[2][8][4];
#pragma unroll
        for (int a = 0; a < 2; a++)
#pragma unroll
            for (int b = 0; b < 8; b++)
#pragma unroll
                for (int c = 0; c < 4; c++) acc[a][b][c] = 0.f;

        auto load_stage = [&](int st, int kt) {
            int k0 = kt * BK;
#pragma unroll
            for (int rep = 0; rep < 4; rep++) {
                int q = tid + rep * 256;
                int r = q >> 3, c8 = (q & 7) << 3;
                cp16(&SA(st, r, c8), Ag + (size_t)(bm0 + r) * KT + k0 + c8);
            }
#pragma unroll
            for (int rep = 0; rep < 4; rep++) {
                int q = tid + rep * 256;
                int r = q >> 3, c8 = (q & 7) << 3;
                cp16(&SB(st, r, c8), Bg + (size_t)(bn0 + r) * KT + k0 + c8);
            }
            asm volatile("cp.async.commit_group;\n" ::);
        };

        load_stage(0, 0);
        if (TILES > 1) load_stage(1, 1);
#pragma unroll 1
        for (int kt = 0; kt < TILES; ++kt) {
            int buf = kt & 1;
            if (kt + 1 < TILES) {
                asm volatile("cp.async.wait_group 1;\n" ::);
            } else {
                asm volatile("cp.async.wait_group 0;\n" ::);
            }
            __syncthreads();
#pragma unroll
            for (int kk = 0; kk < BK; kk += 16) {
                uint32_t af[2][4];
                int arow = wm + (lane & 15);
                int acol = kk + ((lane & 16) ? 8 : 0);
                ldm4(af[0], &SA(buf, arow, acol));
                ldm4(af[1], &SA(buf, arow + 16, acol));
                int brow0 = wn + ((lane & 16) ? 8 : 0) + (lane & 7);
                int bcol = kk + ((lane & 8) ? 8 : 0);
#pragma unroll
                for (int nj = 0; nj < 4; ++nj) {
                    uint32_t bf[4];
                    ldm4(bf, &SB(buf, brow0 + nj * 16, bcol));
#pragma unroll
                    for (int mi = 0; mi < 2; ++mi) {
                        mma16816(acc[mi][nj * 2], af[mi], bf[0], bf[1]);
                        mma16816(acc[mi][nj * 2 + 1], af[mi], bf[2], bf[3]);
                    }
                }
            }
            __syncthreads();
            if (kt + 2 < TILES) load_stage(buf, kt + 2);
        }

        // ---------------- epilogue: fast LIF + warp-aggregated flagging ----------------
        int gr = lane >> 2;
        int gc = (lane & 3) << 1;
#pragma unroll
        for (int mi = 0; mi < 2; ++mi)
#pragma unroll
            for (int jn = 0; jn < 8; ++jn) {
                int n = bn0 + wn + jn * 8 + gc;
#pragma unroll
                for (int h2 = 0; h2 < 2; ++h2) {
                    int row = bm0 + wm + mi * 16 + gr + h2 * 8;
                    size_t base = (size_t)row * NT + n;
#pragma unroll
                    for (int cc = 0; cc < 2; ++cc) {
                        size_t idx = base + cc;
                        float val = __fmul_rn(acc[mi][jn][h2 * 2 + cc], scale);
                        if (EPI == 1) val = __fadd_rn(val, bgen[n + cc]);
                        float mprev = (EPI == 1) ? g_gen_mem[idx] : g_inf_mem[idx];
                        float mem = __fadd_rn(__fmul_rn(BETA32, mprev), val);
                        bool flag = (fabsf(mem - 1.0f) < MARGIN);
                        uint fmask = __ballot_sync(0xffffffffu, flag);
                        if (flag) {
                            int leader = __ffs(fmask) - 1;
                            int off = __popc(fmask & ((1u << lane) - 1));
                            int bpos = 0;
                            if (lane == leader) bpos = atomicAdd(cnt, __popc(fmask));
                            bpos = __shfl_sync(fmask, bpos, leader);
                            int pos = bpos + off;
                            if (pos < FLAG_CAP) g_flags[EPI - 1][pos] = (uint)idx;
                            continue;   // fix kernel owns all writes for this element
                        }
                        bool sp = (mem >= 1.0f);
                        float spk = sp ? 1.f : 0.f;
                        if (EPI == 1) {
                            g_gen_mem[idx] = sp ? 0.f : mem;
                            if (sp) g_lr1[idx] = (unsigned char)(step + 1);
                            err[idx] = __fmul_rn(__fsub_rn(bu[idx], spk), es);
                            if (last) {
                                pred[idx] = spk;
                                comb[(size_t)row * (I_ + H_) + (n + cc)] = mem;
                            }
                        } else {
                            g_inf_mem[idx] = sp ? 0.f : mem;
                            if (sp) g_lr2[idx] = (unsigned char)(step + 1);
                            float c9 = __fmul_rn(cur[idx], 0.9f);
                            float s1 = __fmul_rn(spk, 0.1f);
                            cur[idx] = __fadd_rn(c9, s1);
                            if (last) comb[(size_t)row * (I_ + H_) + I_ + (n + cc)] = mem;
                        }
                    }
                }
            }
        __syncthreads();   // smem reuse across persistent tiles
    }
#undef SA
#undef SB
}

// ---------------- exact fix: recompute flagged elements with the Eigen chain ----------------
template <int LAYER>
__global__ void fix_kernel(const float* __restrict__ bgen, const float* __restrict__ bu,
                           const float* __restrict__ errscale, float* __restrict__ cur,
                           float* __restrict__ err, float* __restrict__ comb,
                           float* __restrict__ pred, int step, int last) {
    constexpr int K = (LAYER == 1) ? H_ : I_;
    constexpr int NT = (LAYER == 1) ? I_ : H_;
    constexpr int SHIFT = (LAYER == 1) ? 10 : 11;
    int cnt = g_flag_cnt[step * 2 + (LAYER - 1)];
    if (cnt > FLAG_CAP) cnt = FLAG_CAP;
    float es = (LAYER == 1) ? *errscale : 0.f;
    for (int e = blockIdx.x * blockDim.x + threadIdx.x; e < cnt; e += gridDim.x * blockDim.x) {
        uint idx = g_flags[LAYER - 1][e];
        int row = (int)(idx >> SHIFT);
        int n = (int)(idx & (NT - 1));
        const float* w = (LAYER == 1) ? (g_WQ + (size_t)n * H_) : (g_W1T + (size_t)n * I_);
        int t0 = (LAYER == 1) ? g_lr1[idx] : g_lr2[idx];
        float mem = 0.f;
        for (int t = t0; t <= step; ++t) {
            const float* X = ((LAYER == 1) ? g_X1hist : g_X2hist) + ((size_t)t * B_ + row) * K;
            float acc = 0.f;
            const float4* X4 = (const float4*)X;
            const float4* W4 = (const float4*)w;
#pragma unroll 4
            for (int k = 0; k < K / 4; ++k) {
                float4 xv = __ldg(X4 + k), wv = __ldg(W4 + k);
                acc = __fmaf_rn(xv.x, wv.x, acc);   // strict ascending-k chain
                acc = __fmaf_rn(xv.y, wv.y, acc);
                acc = __fmaf_rn(xv.z, wv.z, acc);
                acc = __fmaf_rn(xv.w, wv.w, acc);
            }
            float val = (LAYER == 1) ? __fadd_rn(acc, bgen[n]) : acc;
            mem = __fadd_rn(__fmul_rn(BETA32, mem), val);   // eager: mul then add
        }
        bool sp = (mem >= 1.0f);
        float spk = sp ? 1.f : 0.f;
        if (LAYER == 1) {
            g_gen_mem[idx] = sp ? 0.f : mem;
            if (sp) g_lr1[idx] = (unsigned char)(step + 1);
            err[idx] = __fmul_rn(__fsub_rn(bu[idx], spk), es);
            if (last) {
                pred[idx] = spk;
                comb[(size_t)row * (I_ + H_) + n] = mem;
            }
        } else {
            g_inf_mem[idx] = sp ? 0.f : mem;
            if (sp) g_lr2[idx] = (unsigned char)(step + 1);
            float c9 = __fmul_rn(cur[idx], 0.9f);
            float s1 = __fmul_rn(spk, 0.1f);
            cur[idx] = __fadd_rn(c9, s1);
            if (last) comb[(size_t)row * (I_ + H_) + I_ + n] = mem;
        }
    }
}

// ---------------- launch ----------------
extern "C" void kernel_launch(void* const* d_in, const int* in_sizes, int n_in,
                              void* d_out, int out_size) {
    const float* bu   = (const float*)d_in[0];
    const float* td   = (const float*)d_in[1];
    const float* W    = (const float*)d_in[2];
    const float* bgen = (const float*)d_in[3];
    const float* gs   = (const float*)d_in[4];
    const float* bs   = (const float*)d_in[5];
    const float* ge   = (const float*)d_in[6];
    const float* be   = (const float*)d_in[7];
    const float* esc  = (const float*)d_in[8];
    float* out  = (float*)d_out;
    float* cur  = out;                                   // [B, H]
    float* err  = out + (size_t)B_ * H_;                 // [B, I]
    float* comb = err + (size_t)B_ * I_;                 // [B, I+H]
    float* pred = comb + (size_t)B_ * (I_ + H_);         // [B, I]

    constexpr int SMEM_BYTES = 4 * 128 * 72 * 2;         // 73728: 2 stages x (A+B)
    cudaFuncSetAttribute(gemm_fast<1, H_, I_>,
                         cudaFuncAttributeMaxDynamicSharedMemorySize, SMEM_BYTES);
    cudaFuncSetAttribute(gemm_fast<2, I_, H_>,
                         cudaFuncAttributeMaxDynamicSharedMemorySize, SMEM_BYTES);

    reduce_quant_kernel<<<512, 256>>>(W);                // launch 1 (fused)

    for (int s = 0; s < 5; ++s) {
        int last = (s == 4) ? 1 : 0;
        ln_kernel<H_, 1><<<B_, 256>>>(s == 0 ? td : cur, gs, bs, s, cur, s == 0 ? 1 : 0);
        gemm_fast<1, H_, I_><<<296, 256, SMEM_BYTES>>>(
            bgen, bu, esc, cur, err, comb, pred, s, last);   // launch 3 (s=0)
        fix_kernel<1><<<512, 256>>>(bgen, bu, esc, cur, err, comb, pred, s, last);
        // ^ launch 4 (s=0): ncu capture slot — measures the fix cost
        ln_kernel<I_, 2><<<B_, 256>>>(err, ge, be, s, nullptr, 0);
        gemm_fast<2, I_, H_><<<296, 256, SMEM_BYTES>>>(
            bgen, bu, esc, cur, err, comb, pred, s, last);
        fix_kernel<2><<<512, 256>>>(bgen, bu, esc, cur, err, comb, pred, s, last);
    }
}

// round 13
// speedup vs baseline: 1.5326x; 1.5326x over previous
#include <cuda_runtime.h>
#include <cuda_fp16.h>
#include <cstdint>

#define B_ 8192
#define I_ 1024
#define H_ 2048
#define BETA32 ((float)0.9512294245007140)
#define MARGIN 2e-3f
#define FLAG_CAP (4 * 1024 * 1024)

typedef unsigned int uint;

// ---------------- device-global scratch (no mallocs allowed) ----------------
__device__ float  g_gen_mem[(size_t)B_ * I_];
__device__ float  g_inf_mem[(size_t)B_ * H_];
__device__ unsigned char g_lr1[(size_t)B_ * I_];    // last-reset step, gen layer
__device__ unsigned char g_lr2[(size_t)B_ * H_];    // last-reset step, inf layer
__device__ float  g_X1hist[(size_t)5 * B_ * H_];    // exact LN(current) per step
__device__ float  g_X2hist[(size_t)5 * B_ * I_];    // exact LN(error) per step
__device__ __half g_X1h[(size_t)B_ * H_];           // fp16(hi) of LN(current)
__device__ __half g_X2h[(size_t)B_ * I_];
__device__ __half g_W1h[(size_t)I_ * H_];           // ternary fp16: rows n=i, cols k=h
__device__ __half g_W2h[(size_t)H_ * I_];           // ternary fp16: rows n=h, cols k=i
__device__ float  g_WQ[(size_t)I_ * H_];            // exact wq [i][h]
__device__ float  g_W1T[(size_t)H_ * I_];           // exact wq^T [h][i]
__device__ double g_partials[512];
__device__ int    g_qcnt;
__device__ int    g_qcnt2;
__device__ volatile int g_ready;
__device__ float  g_sc[2];                          // [0]=scale, [1]=scale+eps
__device__ int    g_flag_cnt[12];
__device__ uint   g_flags[2][FLAG_CAP];
__device__ float  g_dots[(size_t)5 * FLAG_CAP];     // per-(flag,step) exact dots

// ---------------- helpers ----------------
__device__ __forceinline__ double warp_sumd(double v) {
#pragma unroll
    for (int o = 16; o; o >>= 1) v += __shfl_xor_sync(0xffffffffu, v, o);
    return v;
}
__device__ __forceinline__ void two_sum(float a, float b, float& s, float& e) {
    s = __fadd_rn(a, b);
    float bp = __fsub_rn(s, a);
    e = __fadd_rn(__fsub_rn(a, __fsub_rn(s, bp)), __fsub_rn(b, bp));
}
__device__ __forceinline__ void kahan_add(float v, float& s, float& c) {
    float t, e;
    two_sum(s, v, t, e);
    s = t;
    c = __fadd_rn(c, e);
}
__device__ __forceinline__ void cp16(void* sm, const void* gm) {
    uint32_t s = (uint32_t)__cvta_generic_to_shared(sm);
    asm volatile("cp.async.cg.shared.global [%0], [%1], 16;\n" ::"r"(s), "l"(gm));
}
__device__ __forceinline__ void ldm4(uint32_t r[4], const __half* p) {
    uint32_t a = (uint32_t)__cvta_generic_to_shared(p);
    asm volatile("ldmatrix.sync.aligned.m8n8.x4.shared.b16 {%0,%1,%2,%3},[%4];\n"
                 : "=r"(r[0]), "=r"(r[1]), "=r"(r[2]), "=r"(r[3]) : "r"(a));
}
__device__ __forceinline__ void mma16816(float c[4], const uint32_t a[4], uint32_t b0, uint32_t b1) {
    asm volatile(
        "mma.sync.aligned.m16n8k16.row.col.f32.f16.f16.f32 "
        "{%0,%1,%2,%3},{%4,%5,%6,%7},{%8,%9},{%0,%1,%2,%3};\n"
        : "+f"(c[0]), "+f"(c[1]), "+f"(c[2]), "+f"(c[3])
        : "r"(a[0]), "r"(a[1]), "r"(a[2]), "r"(a[3]), "r"(b0), "r"(b1));
}

// ---------------- fused |W| reduce + scale + quantize (persistent, self-resetting) ----------------
__global__ __launch_bounds__(256) void reduce_quant_kernel(const float* __restrict__ W) {
    double s = 0.0;
    for (int i = blockIdx.x * blockDim.x + threadIdx.x; i < I_ * H_; i += gridDim.x * blockDim.x)
        s += (double)fabsf(W[i]);
    s = warp_sumd(s);
    __shared__ double sh[8];
    __shared__ bool amLast;
    int lane = threadIdx.x & 31, wid = threadIdx.x >> 5;
    if (lane == 0) sh[wid] = s;
    __syncthreads();
    if (threadIdx.x == 0) {
        double t = 0.0;
        for (int i = 0; i < 8; i++) t += sh[i];
        g_partials[blockIdx.x] = t;
        __threadfence();
        int prev = atomicAdd(&g_qcnt, 1);
        amLast = (prev == (int)gridDim.x - 1);
    }
    __syncthreads();
    if (amLast && threadIdx.x == 0) {
        double t = 0.0;
        for (int i = 0; i < 512; i++) t += g_partials[i];   // fixed order -> deterministic
        float Sf = (float)t;
        float scale = Sf / 2097152.0f;                      // exact (2^21)
        g_sc[0] = scale;
        g_sc[1] = __fadd_rn(scale, 1e-5f);
        g_qcnt = 0;
        __threadfence();
        g_ready = 1;
    }
    if (threadIdx.x == 0) {
        while (g_ready == 0) {}
    }
    __syncthreads();
    float d = ((volatile float*)g_sc)[1];
    float sc = ((volatile float*)g_sc)[0];
    for (int idx = blockIdx.x * 256 + threadIdx.x; idx < I_ * H_; idx += 512 * 256) {
        float t = rintf(W[idx] / d);                        // CR div + round-half-even
        t = fminf(1.f, fmaxf(-1.f, t));
        float wq = __fmul_rn(t, sc);                        // exact (t in {-1,0,1})
        int i = idx >> 11;
        int h = idx & (H_ - 1);
        g_WQ[(size_t)i * H_ + h] = wq;
        g_W1T[(size_t)h * I_ + i] = wq;
        __half th = __float2half_rn(t);
        g_W1h[(size_t)i * H_ + h] = th;
        g_W2h[(size_t)h * I_ + i] = th;
    }
    __threadfence();
    if (threadIdx.x == 0) {
        int prev2 = atomicAdd(&g_qcnt2, 1);
        if (prev2 == (int)gridDim.x - 1) {
            g_ready = 0;
            g_qcnt2 = 0;
        }
    }
}

// ---------------- layer norm (Kahan fp32 stats; eager-XLA-exact elementwise) ----------------
template <int N, int WHICH>
__global__ __launch_bounds__(256) void ln_kernel(const float* __restrict__ x,
                                                 const float* __restrict__ g,
                                                 const float* __restrict__ bb,
                                                 int step, float* __restrict__ cur, int first) {
    constexpr int PER = N / 256;
    const int b = blockIdx.x;
    const float* xr = x + (size_t)b * N;
    float* hist = ((WHICH == 1) ? g_X1hist : g_X2hist) + ((size_t)step * B_ + b) * N;
    __half* yh = ((WHICH == 1) ? g_X1h : g_X2h) + (size_t)b * N;
    float v[PER];
    float s = 0.f, sc = 0.f;
#pragma unroll
    for (int j = 0; j < PER; j++) {
        float t = xr[threadIdx.x + j * 256];
        v[j] = t;
        kahan_add(t, s, sc);
    }
#pragma unroll
    for (int o = 16; o; o >>= 1) {
        float so = __shfl_xor_sync(0xffffffffu, s, o);
        float co = __shfl_xor_sync(0xffffffffu, sc, o);
        float t, e;
        two_sum(s, so, t, e);
        s = t;
        sc = __fadd_rn(sc, __fadd_rn(co, e));
    }
    __shared__ float shs[8], shc[8];
    __shared__ float fmu, frstd;
    int lane = threadIdx.x & 31, wid = threadIdx.x >> 5;
    if (lane == 0) { shs[wid] = s; shc[wid] = sc; }
    __syncthreads();
    if (threadIdx.x == 0) {
        double a = 0.0;
        for (int i = 0; i < 8; i++) a += (double)shs[i] + (double)shc[i];
        float Sf = (float)a;                     // ~CR f32 sum
        fmu = Sf / (float)N;                     // exact (N power of 2)
    }
    __syncthreads();
    float mu = fmu;
    float s2 = 0.f, s2c = 0.f;
#pragma unroll
    for (int j = 0; j < PER; j++) {
        float d = __fsub_rn(v[j], mu);
        float dd = __fmul_rn(d, d);
        kahan_add(dd, s2, s2c);
    }
#pragma unroll
    for (int o = 16; o; o >>= 1) {
        float so = __shfl_xor_sync(0xffffffffu, s2, o);
        float co = __shfl_xor_sync(0xffffffffu, s2c, o);
        float t, e;
        two_sum(s2, so, t, e);
        s2 = t;
        s2c = __fadd_rn(s2c, __fadd_rn(co, e));
    }
    if (lane == 0) { shs[wid] = s2; shc[wid] = s2c; }
    __syncthreads();
    if (threadIdx.x == 0) {
        double b2 = 0.0;
        for (int i = 0; i < 8; i++) b2 += (double)shs[i] + (double)shc[i];
        float S2f = (float)b2;
        float var = S2f / (float)N;              // exact
        float vp = __fadd_rn(var, 1e-5f);
        frstd = __fdiv_rn(1.0f, __fsqrt_rn(vp));
    }
    __syncthreads();
    float mu2 = fmu;
    float rstd = frstd;
#pragma unroll
    for (int j = 0; j < PER; j++) {
        int c = threadIdx.x + j * 256;
        float t1 = __fsub_rn(v[j], mu2);
        float t2 = __fmul_rn(t1, rstd);
        float t3 = __fmul_rn(t2, g[c]);          // separate mul (no fma)
        float yv = __fadd_rn(t3, bb[c]);         // separate add
        hist[c] = yv;                            // exact fp32 for fix kernels
        yh[c] = __float2half_rn(yv);             // hi only (fix covers the tail)
    }
    if (WHICH == 1 && first) {                   // step-0: fold in init
        for (int c = threadIdx.x; c < H_; c += 256) {
            size_t ii = (size_t)b * H_ + c;
            cur[ii] = xr[c];
            g_inf_mem[ii] = 0.f;
            g_lr2[ii] = 0;
        }
        for (int c = threadIdx.x; c < I_; c += 256) {
            size_t ii = (size_t)b * I_ + c;
            g_gen_mem[ii] = 0.f;
            g_lr1[ii] = 0;
        }
        if (b == 0 && threadIdx.x < 12) g_flag_cnt[threadIdx.x] = 0;
    }
}

// ---------------- fast tensor GEMM (fp16 hi-only, fp32 acc), persistent CTAs, BK=64 ----------------
template <int EPI, int KT, int NT>
__global__ __launch_bounds__(256, 2) void gemm_fast(
    const float* __restrict__ bgen, const float* __restrict__ bu,
    const float* __restrict__ errscale, float* __restrict__ cur,
    float* __restrict__ err, float* __restrict__ comb, float* __restrict__ pred,
    int step, int last) {
    const __half* Ag = (EPI == 1) ? g_X1h : g_X2h;
    const __half* Bg = (EPI == 1) ? g_W1h : g_W2h;
    constexpr int BK = 64;
    constexpr int LDS = 72;
    constexpr int TILES = KT / BK;
    constexpr int TN = NT / 128;
    constexpr int NTILES = (B_ / 128) * TN;

    extern __shared__ __align__(16) __half smem_h[];
    __half* sAp = smem_h;                        // [2][128][LDS]
    __half* sBp = smem_h + 2 * 128 * LDS;        // [2][128][LDS]
#define SA(st, r, c) sAp[((st) * 128 + (r)) * LDS + (c)]
#define SB(st, r, c) sBp[((st) * 128 + (r)) * LDS + (c)]

    const int tid = threadIdx.x;
    const int lane = tid & 31, wid = tid >> 5;
    const int wm = (wid & 3) * 32, wn = (wid >> 2) * 64;
    const float scale = g_sc[0];
    const float es = (EPI == 1) ? *errscale : 0.f;
    int* cnt = &g_flag_cnt[step * 2 + (EPI - 1)];

    for (int tile = blockIdx.x; tile < NTILES; tile += gridDim.x) {
        const int mb = tile / TN, nb = tile % TN;
        const int bm0 = mb * 128, bn0 = nb * 128;

        float acc[2][8][4];
#pragma unroll
        for (int a = 0; a < 2; a++)
#pragma unroll
            for (int b = 0; b < 8; b++)
#pragma unroll
                for (int c = 0; c < 4; c++) acc[a][b][c] = 0.f;

        auto load_stage = [&](int st, int kt) {
            int k0 = kt * BK;
#pragma unroll
            for (int rep = 0; rep < 4; rep++) {
                int q = tid + rep * 256;
                int r = q >> 3, c8 = (q & 7) << 3;
                cp16(&SA(st, r, c8), Ag + (size_t)(bm0 + r) * KT + k0 + c8);
            }
#pragma unroll
            for (int rep = 0; rep < 4; rep++) {
                int q = tid + rep * 256;
                int r = q >> 3, c8 = (q & 7) << 3;
                cp16(&SB(st, r, c8), Bg + (size_t)(bn0 + r) * KT + k0 + c8);
            }
            asm volatile("cp.async.commit_group;\n" ::);
        };

        load_stage(0, 0);
        if (TILES > 1) load_stage(1, 1);
#pragma unroll 1
        for (int kt = 0; kt < TILES; ++kt) {
            int buf = kt & 1;
            if (kt + 1 < TILES) {
                asm volatile("cp.async.wait_group 1;\n" ::);
            } else {
                asm volatile("cp.async.wait_group 0;\n" ::);
            }
            __syncthreads();
#pragma unroll
            for (int kk = 0; kk < BK; kk += 16) {
                uint32_t af[2][4];
                int arow = wm + (lane & 15);
                int acol = kk + ((lane & 16) ? 8 : 0);
                ldm4(af[0], &SA(buf, arow, acol));
                ldm4(af[1], &SA(buf, arow + 16, acol));
                int brow0 = wn + ((lane & 16) ? 8 : 0) + (lane & 7);
                int bcol = kk + ((lane & 8) ? 8 : 0);
#pragma unroll
                for (int nj = 0; nj < 4; ++nj) {
                    uint32_t bf[4];
                    ldm4(bf, &SB(buf, brow0 + nj * 16, bcol));
#pragma unroll
                    for (int mi = 0; mi < 2; ++mi) {
                        mma16816(acc[mi][nj * 2], af[mi], bf[0], bf[1]);
                        mma16816(acc[mi][nj * 2 + 1], af[mi], bf[2], bf[3]);
                    }
                }
            }
            __syncthreads();
            if (kt + 2 < TILES) load_stage(buf, kt + 2);
        }

        // ---------------- epilogue: fast LIF + warp-aggregated flagging ----------------
        int gr = lane >> 2;
        int gc = (lane & 3) << 1;
#pragma unroll
        for (int mi = 0; mi < 2; ++mi)
#pragma unroll
            for (int jn = 0; jn < 8; ++jn) {
                int n = bn0 + wn + jn * 8 + gc;
#pragma unroll
                for (int h2 = 0; h2 < 2; ++h2) {
                    int row = bm0 + wm + mi * 16 + gr + h2 * 8;
                    size_t base = (size_t)row * NT + n;
#pragma unroll
                    for (int cc = 0; cc < 2; ++cc) {
                        size_t idx = base + cc;
                        float val = __fmul_rn(acc[mi][jn][h2 * 2 + cc], scale);
                        if (EPI == 1) val = __fadd_rn(val, bgen[n + cc]);
                        float mprev = (EPI == 1) ? g_gen_mem[idx] : g_inf_mem[idx];
                        float mem = __fadd_rn(__fmul_rn(BETA32, mprev), val);
                        bool flag = (fabsf(mem - 1.0f) < MARGIN);
                        uint fmask = __ballot_sync(0xffffffffu, flag);
                        if (flag) {
                            int leader = __ffs(fmask) - 1;
                            int off = __popc(fmask & ((1u << lane) - 1));
                            int bpos = 0;
                            if (lane == leader) bpos = atomicAdd(cnt, __popc(fmask));
                            bpos = __shfl_sync(fmask, bpos, leader);
                            int pos = bpos + off;
                            if (pos < FLAG_CAP) g_flags[EPI - 1][pos] = (uint)idx;
                            continue;   // fix kernels own all writes for this element
                        }
                        bool sp = (mem >= 1.0f);
                        float spk = sp ? 1.f : 0.f;
                        if (EPI == 1) {
                            g_gen_mem[idx] = sp ? 0.f : mem;
                            if (sp) g_lr1[idx] = (unsigned char)(step + 1);
                            err[idx] = __fmul_rn(__fsub_rn(bu[idx], spk), es);
                            if (last) {
                                pred[idx] = spk;
                                comb[(size_t)row * (I_ + H_) + (n + cc)] = mem;
                            }
                        } else {
                            g_inf_mem[idx] = sp ? 0.f : mem;
                            if (sp) g_lr2[idx] = (unsigned char)(step + 1);
                            float c9 = __fmul_rn(cur[idx], 0.9f);
                            float s1 = __fmul_rn(spk, 0.1f);
                            cur[idx] = __fadd_rn(c9, s1);
                            if (last) comb[(size_t)row * (I_ + H_) + I_ + (n + cc)] = mem;
                        }
                    }
                }
            }
        __syncthreads();   // smem reuse across persistent tiles
    }
#undef SA
#undef SB
}

// ---------------- fix stage 1: exact dots, one thread per (flag, step-segment) ----------------
template <int LAYER>
__global__ __launch_bounds__(64) void fix_dots(int step) {
    constexpr int K = (LAYER == 1) ? H_ : I_;
    constexpr int NT = (LAYER == 1) ? I_ : H_;
    constexpr int SHIFT = (LAYER == 1) ? 10 : 11;
    int cnt = g_flag_cnt[step * 2 + (LAYER - 1)];
    if (cnt > FLAG_CAP) cnt = FLAG_CAP;
    const int nsteps = step + 1;
    const int total = cnt * nsteps;
    for (int q = blockIdx.x * 64 + threadIdx.x; q < total; q += gridDim.x * 64) {
        int e = q / nsteps;
        int t = q - e * nsteps;
        uint idx = g_flags[LAYER - 1][e];
        int t0 = (LAYER == 1) ? g_lr1[idx] : g_lr2[idx];
        if (t < t0) continue;
        int row = (int)(idx >> SHIFT);
        int n = (int)(idx & (NT - 1));
        const float4* X4 = (const float4*)(((LAYER == 1) ? g_X1hist : g_X2hist) +
                                           ((size_t)t * B_ + row) * K);
        const float4* W4 = (const float4*)(((LAYER == 1) ? g_WQ : g_W1T) + (size_t)n * K);
        float acc = 0.f;
#pragma unroll 8
        for (int k = 0; k < K / 4; ++k) {
            float4 xv = __ldg(X4 + k), wv = __ldg(W4 + k);
            acc = __fmaf_rn(xv.x, wv.x, acc);   // strict ascending-k chain
            acc = __fmaf_rn(xv.y, wv.y, acc);
            acc = __fmaf_rn(xv.z, wv.z, acc);
            acc = __fmaf_rn(xv.w, wv.w, acc);
        }
        g_dots[(size_t)e * 5 + t] = acc;
    }
}

// ---------------- fix stage 2: fold dots (exact eager beta-recurrence) + writes ----------------
template <int LAYER>
__global__ void fix_apply(const float* __restrict__ bgen, const float* __restrict__ bu,
                          const float* __restrict__ errscale, float* __restrict__ cur,
                          float* __restrict__ err, float* __restrict__ comb,
                          float* __restrict__ pred, int step, int last) {
    constexpr int NT = (LAYER == 1) ? I_ : H_;
    constexpr int SHIFT = (LAYER == 1) ? 10 : 11;
    int cnt = g_flag_cnt[step * 2 + (LAYER - 1)];
    if (cnt > FLAG_CAP) cnt = FLAG_CAP;
    float es = (LAYER == 1) ? *errscale : 0.f;
    for (int e = blockIdx.x * blockDim.x + threadIdx.x; e < cnt; e += gridDim.x * blockDim.x) {
        uint idx = g_flags[LAYER - 1][e];
        int row = (int)(idx >> SHIFT);
        int n = (int)(idx & (NT - 1));
        int t0 = (LAYER == 1) ? g_lr1[idx] : g_lr2[idx];
        float mem = 0.f;
        for (int t = t0; t <= step; ++t) {
            float dot = g_dots[(size_t)e * 5 + t];
            float val = (LAYER == 1) ? __fadd_rn(dot, bgen[n]) : dot;
            mem = __fadd_rn(__fmul_rn(BETA32, mem), val);   // eager: mul then add
        }
        bool sp = (mem >= 1.0f);
        float spk = sp ? 1.f : 0.f;
        if (LAYER == 1) {
            g_gen_mem[idx] = sp ? 0.f : mem;
            if (sp) g_lr1[idx] = (unsigned char)(step + 1);
            err[idx] = __fmul_rn(__fsub_rn(bu[idx], spk), es);
            if (last) {
                pred[idx] = spk;
                comb[(size_t)row * (I_ + H_) + n] = mem;
            }
        } else {
            g_inf_mem[idx] = sp ? 0.f : mem;
            if (sp) g_lr2[idx] = (unsigned char)(step + 1);
            float c9 = __fmul_rn(cur[idx], 0.9f);
            float s1 = __fmul_rn(spk, 0.1f);
            cur[idx] = __fadd_rn(c9, s1);
            if (last) comb[(size_t)row * (I_ + H_) + I_ + n] = mem;
        }
    }
}

// ---------------- launch ----------------
extern "C" void kernel_launch(void* const* d_in, const int* in_sizes, int n_in,
                              void* d_out, int out_size) {
    const float* bu   = (const float*)d_in[0];
    const float* td   = (const float*)d_in[1];
    const float* W    = (const float*)d_in[2];
    const float* bgen = (const float*)d_in[3];
    const float* gs   = (const float*)d_in[4];
    const float* bs   = (const float*)d_in[5];
    const float* ge   = (const float*)d_in[6];
    const float* be   = (const float*)d_in[7];
    const float* esc  = (const float*)d_in[8];
    float* out  = (float*)d_out;
    float* cur  = out;                                   // [B, H]
    float* err  = out + (size_t)B_ * H_;                 // [B, I]
    float* comb = err + (size_t)B_ * I_;                 // [B, I+H]
    float* pred = comb + (size_t)B_ * (I_ + H_);         // [B, I]

    constexpr int SMEM_BYTES = 4 * 128 * 72 * 2;         // 73728: 2 stages x (A+B)
    cudaFuncSetAttribute(gemm_fast<1, H_, I_>,
                         cudaFuncAttributeMaxDynamicSharedMemorySize, SMEM_BYTES);
    cudaFuncSetAttribute(gemm_fast<2, I_, H_>,
                         cudaFuncAttributeMaxDynamicSharedMemorySize, SMEM_BYTES);

    reduce_quant_kernel<<<512, 256>>>(W);                // launch 1 (fused)

    for (int s = 0; s < 5; ++s) {
        int last = (s == 4) ? 1 : 0;
        ln_kernel<H_, 1><<<B_, 256>>>(s == 0 ? td : cur, gs, bs, s, cur, s == 0 ? 1 : 0);
        gemm_fast<1, H_, I_><<<296, 256, SMEM_BYTES>>>(
            bgen, bu, esc, cur, err, comb, pred, s, last);
        fix_dots<1><<<1184, 64>>>(s);
        // ^ launch 4 (s=0): ncu capture slot — verifies the new dots cost
        fix_apply<1><<<512, 256>>>(bgen, bu, esc, cur, err, comb, pred, s, last);
        ln_kernel<I_, 2><<<B_, 256>>>(err, ge, be, s, nullptr, 0);
        gemm_fast<2, I_, H_><<<296, 256, SMEM_BYTES>>>(
            bgen, bu, esc, cur, err, comb, pred, s, last);
        fix_dots<2><<<1184, 64>>>(s);
        fix_apply<2><<<512, 256>>>(bgen, bu, esc, cur, err, comb, pred, s, last);
    }
}